// round 12
// baseline (speedup 1.0000x reference)
#include <cuda_runtime.h>
#include <math.h>

// Problem constants
#define Bq 16
#define Tq 750
#define Fq 4096
#define Cq 20
#define Kq 93           // T / 8
#define F4 (Fq/4)       // 1024 float4 per row
#define NROWS (Bq*Tq)   // 12000

#define CHUNK 64        // float4 per F-chunk (16 chunks per row)
#define NCH (F4/CHUNK)
#define RPB 16          // rows per block
#define TPAD 768        // padded T for transposed cas

// Output layout (concatenated in reference return order, float32)
#define OFF_SA   0L
#define OFF_SB   320L
#define OFF_FA   640L
#define OFF_FB   (OFF_FA + (long)Bq*Kq*Fq)
#define OFF_FEAT (OFF_FB + (long)Bq*Kq*Fq)
#define OFF_CS   (OFF_FEAT + (long)NROWS*Fq)

// Scratch (static device globals; no runtime allocation)
__device__ float g_casT[Bq*Cq*TPAD];
__device__ float g_mag[NROWS];
__device__ int   g_idx_act[Bq*Kq];
__device__ int   g_idx_bkg[Bq*Kq];
__device__ float g_sa[Bq*Cq];
__device__ float g_sb[Bq*Cq];

typedef unsigned long long ull;

// Packed f32x2 helpers (Blackwell FFMA2 — only reachable via PTX)
__device__ __forceinline__ ull fma2(ull a, ull b, ull c)
{
    ull d;
    asm("fma.rn.f32x2 %0, %1, %2, %3;" : "=l"(d) : "l"(a), "l"(b), "l"(c));
    return d;
}
__device__ __forceinline__ ull mul2(ull a, ull b)
{
    ull d;
    asm("mul.rn.f32x2 %0, %1, %2;" : "=l"(d) : "l"(a), "l"(b));
    return d;
}
__device__ __forceinline__ float pairsum(ull v)
{
    float lo, hi;
    asm("mov.b64 {%0,%1}, %2;" : "=f"(lo), "=f"(hi) : "l"(v));
    return lo + hi;
}

// Monotone float <-> uint order map (total order)
__device__ __forceinline__ unsigned int fmap(float f)
{
    unsigned int u = __float_as_uint(f);
    return (u & 0x80000000u) ? ~u : (u | 0x80000000u);
}
__device__ __forceinline__ float funmap(unsigned int u)
{
    return (u & 0x80000000u) ? __uint_as_float(u ^ 0x80000000u)
                             : __uint_as_float(~u);
}

__device__ __forceinline__ void bar_named(int id)
{
    asm volatile("bar.sync %0, 128;" :: "r"(id) : "memory");
}

// Dummy no-op kernel: shifts the ncu capture window onto k_main.
__global__ void k_nop() {}

// 128-thread k-th largest using a named barrier (two instances run
// concurrently in one 256-thread block). 4-bit radix descent.
__device__ unsigned int kth_largest_h(const unsigned int* __restrict__ v, int n,
                                      int k, int* s_hist, int ltid, int barid)
{
    unsigned int prefix = 0;
    for (int shift = 28; shift >= 0; shift -= 4) {
        if (ltid < 16) s_hist[ltid] = 0;
        bar_named(barid);
        const unsigned int mask_hi = (shift == 28) ? 0u : (0xFFFFFFFFu << (shift + 4));
        for (int t = ltid; t < n; t += 128) {
            unsigned int x = v[t];
            if ((x & mask_hi) == prefix)
                atomicAdd(&s_hist[(x >> shift) & 15], 1);
        }
        bar_named(barid);
        int kk = k;
        int d = 15;
        for (; d > 0; d--) {
            int c = s_hist[d];
            if (kk <= c) break;
            kk -= c;
        }
        prefix |= (unsigned int)d << shift;
        k = kk;
        bar_named(barid);
    }
    return prefix;
}

// ---------------------------------------------------------------------------
// K1: fused stream kernel. Block = 256 threads = 8 warps = 16 rows (2/warp).
// x/mask/W cp.async-staged (double-buffered). GEMM uses packed f32x2 FFMA2:
// one LDS.128 yields two f32x2 operands with zero pack instructions, halving
// fma-pipe instruction count. Feature copy uses streaming stores (__stcs).
// ---------------------------------------------------------------------------
extern __shared__ float4 sm_dyn[];

__global__ __launch_bounds__(256, 2) void k_main(const float4* __restrict__ x4,
                                                 const float4* __restrict__ m4,
                                                 const float4* __restrict__ w4,
                                                 float* __restrict__ out)
{
    float4* xsh = sm_dyn;                 // [2][RPB*CHUNK]  (2 x 1024)
    float4* msh = sm_dyn + 2048;          // [2][RPB*CHUNK]
    float4* wsh = sm_dyn + 4096;          // [2][Cq*CHUNK]   (2 x 1280)

    const int tid  = threadIdx.x;
    const int wid  = tid >> 5;
    const int lane = tid & 31;
    const int rbase = blockIdx.x * RPB;
    const int r0 = rbase + wid * 2;
    const int r1 = r0 + 1;

    ulonglong2* __restrict__ fa =
        reinterpret_cast<ulonglong2*>(out + OFF_FEAT) + (long)r0 * F4;
    ulonglong2* __restrict__ fb =
        reinterpret_cast<ulonglong2*>(out + OFF_FEAT) + (long)r1 * F4;

    ull acc0[Cq], acc1[Cq];
#pragma unroll
    for (int c = 0; c < Cq; c++) { acc0[c] = 0ull; acc1[c] = 0ull; }
    ull sq0 = 0ull, sq1 = 0ull;

    // stage chunk ch (x, mask, W) into buffer buf; one commit group
    auto stage = [&](int ch, int buf) {
        const int jc = ch * CHUNK;
#pragma unroll
        for (int q = 0; q < (RPB * CHUNK) / 256; q++) {
            int idx = tid + 256 * q;                  // row = idx>>6, col = idx&63
            const float4* sx = x4 + (long)(rbase + (idx >> 6)) * F4 + jc + (idx & (CHUNK - 1));
            const float4* sm_ = m4 + (long)(rbase + (idx >> 6)) * F4 + jc + (idx & (CHUNK - 1));
            unsigned int dx = (unsigned int)__cvta_generic_to_shared(&xsh[buf * 1024 + idx]);
            unsigned int dm = (unsigned int)__cvta_generic_to_shared(&msh[buf * 1024 + idx]);
            asm volatile("cp.async.cg.shared.global [%0], [%1], 16;" :: "r"(dx), "l"(sx));
            asm volatile("cp.async.cg.shared.global [%0], [%1], 16;" :: "r"(dm), "l"(sm_));
        }
#pragma unroll
        for (int q = 0; q < (Cq * CHUNK) / 256; q++) {
            int idx = tid + 256 * q;
            const float4* src = &w4[(idx >> 6) * F4 + jc + (idx & (CHUNK - 1))];
            unsigned int dst = (unsigned int)__cvta_generic_to_shared(&wsh[buf * (Cq * CHUNK) + idx]);
            asm volatile("cp.async.cg.shared.global [%0], [%1], 16;" :: "r"(dst), "l"(src));
        }
        asm volatile("cp.async.commit_group;");
    };

    stage(0, 0);

    for (int ch = 0; ch < NCH; ch++) {
        const int buf = ch & 1;
        asm volatile("cp.async.wait_group 0;");
        __syncthreads();            // chunk ch staged; prior reads of other buf done
        if (ch + 1 < NCH) stage(ch + 1, buf ^ 1);

        const ulonglong2* xb = reinterpret_cast<const ulonglong2*>(&xsh[buf * 1024]);
        const ulonglong2* mb = reinterpret_cast<const ulonglong2*>(&msh[buf * 1024]);
        const ulonglong2* wb = reinterpret_cast<const ulonglong2*>(&wsh[buf * (Cq * CHUNK)]);
        const int jc = ch * CHUNK;
        const int rp0 = (wid * 2) * CHUNK;
        const int rp1 = (wid * 2 + 1) * CHUNK;
#pragma unroll
        for (int ii = 0; ii < CHUNK / 32; ii++) {
            const int jj = lane + 32 * ii;
            const int j  = jc + jj;
            ulonglong2 a0 = xb[rp0 + jj];
            ulonglong2 a1 = xb[rp1 + jj];
            ulonglong2 q0 = mb[rp0 + jj];
            ulonglong2 q1 = mb[rp1 + jj];
            __stcs(&fa[j], a0);
            __stcs(&fb[j], a1);
            sq0 = fma2(a0.x, a0.x, sq0);
            sq0 = fma2(a0.y, a0.y, sq0);
            sq1 = fma2(a1.x, a1.x, sq1);
            sq1 = fma2(a1.y, a1.y, sq1);
            ull p0x = mul2(a0.x, q0.x);
            ull p0y = mul2(a0.y, q0.y);
            ull p1x = mul2(a1.x, q1.x);
            ull p1y = mul2(a1.y, q1.y);
#pragma unroll
            for (int c = 0; c < Cq; c++) {
                ulonglong2 w = wb[c * CHUNK + jj];
                acc0[c] = fma2(p0x, w.x, acc0[c]);
                acc0[c] = fma2(p0y, w.y, acc0[c]);
                acc1[c] = fma2(p1x, w.x, acc1[c]);
                acc1[c] = fma2(p1y, w.y, acc1[c]);
            }
        }
    }

    // collapse packed accumulators, then warp butterfly
    float fa0[Cq], fa1[Cq];
#pragma unroll
    for (int c = 0; c < Cq; c++) { fa0[c] = pairsum(acc0[c]); fa1[c] = pairsum(acc1[c]); }
    float fsq0 = pairsum(sq0), fsq1 = pairsum(sq1);

#pragma unroll
    for (int off = 16; off > 0; off >>= 1) {
        fsq0 += __shfl_xor_sync(0xffffffffu, fsq0, off);
        fsq1 += __shfl_xor_sync(0xffffffffu, fsq1, off);
#pragma unroll
        for (int c = 0; c < Cq; c++) {
            fa0[c] += __shfl_xor_sync(0xffffffffu, fa0[c], off);
            fa1[c] += __shfl_xor_sync(0xffffffffu, fa1[c], off);
        }
    }

    float v0 = 0.f, v1 = 0.f;
#pragma unroll
    for (int c = 0; c < Cq; c++) {
        if (lane == c) { v0 = fa0[c]; v1 = fa1[c]; }
    }

    float mm0 = (lane < Cq) ? v0 : -INFINITY;
    float mm1 = (lane < Cq) ? v1 : -INFINITY;
#pragma unroll
    for (int off = 16; off > 0; off >>= 1) {
        mm0 = fmaxf(mm0, __shfl_xor_sync(0xffffffffu, mm0, off));
        mm1 = fmaxf(mm1, __shfl_xor_sync(0xffffffffu, mm1, off));
    }
    float e0 = (lane < Cq) ? expf(v0 - mm0) : 0.f;
    float e1 = (lane < Cq) ? expf(v1 - mm1) : 0.f;
    float s0 = e0, s1 = e1;
#pragma unroll
    for (int off = 16; off > 0; off >>= 1) {
        s0 += __shfl_xor_sync(0xffffffffu, s0, off);
        s1 += __shfl_xor_sync(0xffffffffu, s1, off);
    }
    if (lane < Cq) {
        out[OFF_CS + (long)r0 * Cq + lane] = e0 / s0;
        out[OFF_CS + (long)r1 * Cq + lane] = e1 / s1;
        const int b0 = r0 / Tq, t0 = r0 - b0 * Tq;
        const int b1 = r1 / Tq, t1 = r1 - b1 * Tq;
        g_casT[(b0 * Cq + lane) * TPAD + t0] = v0;
        g_casT[(b1 * Cq + lane) * TPAD + t1] = v1;
    }
    if (lane == 0) {
        g_mag[r0] = sqrtf(fsq0);
        g_mag[r1] = sqrtf(fsq1);
    }
}

// ---------------------------------------------------------------------------
// K2: per-batch selection. Halves of the block process the act and bkg lists
// concurrently (named barriers). Radix threshold + stable rank-count of the
// ~93 candidates (exact jax.lax.top_k order).
// ---------------------------------------------------------------------------
__global__ __launch_bounds__(256) void k_select(const float* __restrict__ sel)
{
    const int b = blockIdx.x;
    const int tid = threadIdx.x;
    __shared__ unsigned int ua[Tq];
    __shared__ unsigned int ub[Tq];
    __shared__ float red[256];
    __shared__ int s_histA[16];
    __shared__ int s_histB[16];

    float lmax = -INFINITY;
    for (int t = tid; t < Tq; t += 256) {
        float m = g_mag[b * Tq + t];
        ua[t] = __float_as_uint(m);
        lmax = fmaxf(lmax, m);
    }
    red[tid] = lmax;
    __syncthreads();
    for (int s = 128; s > 0; s >>= 1) {
        if (tid < s) red[tid] = fmaxf(red[tid], red[tid + s]);
        __syncthreads();
    }
    const float mx = red[0];
    __syncthreads();

    for (int t = tid; t < Tq; t += 256) {
        float m = __uint_as_float(ua[t]);
        float s = sel[b * Tq + t];
        float va = m * s + 0.0f;
        float vr = (mx - m) * s + 0.0f;
        ua[t] = fmap(va);
        ub[t] = fmap(vr);
    }
    __syncthreads();

    if (tid < 128) {
        const unsigned int thA = kth_largest_h(ua, Tq, Kq, s_histA, tid, 1);
        for (int t = tid; t < Tq; t += 128) {
            unsigned int xA = ua[t];
            if (xA >= thA) {
                int r = 0;
                for (int j = 0; j < Tq; j++) {
                    unsigned int u = ua[j];
                    r += (u > xA) || (u == xA && j < t);
                }
                if (r < Kq) g_idx_act[b * Kq + r] = t;
            }
        }
    } else {
        const int lt = tid - 128;
        const unsigned int thB = kth_largest_h(ub, Tq, Kq, s_histB, lt, 2);
        for (int t = lt; t < Tq; t += 128) {
            unsigned int xB = ub[t];
            if (xB >= thB) {
                int r = 0;
                for (int j = 0; j < Tq; j++) {
                    unsigned int u = ub[j];
                    r += (u > xB) || (u == xB && j < t);
                }
                if (r < Kq) g_idx_bkg[b * Kq + r] = t;
            }
        }
    }
}

// ---------------------------------------------------------------------------
// K3: gather feat_act / feat_bkg rows from x.
// ---------------------------------------------------------------------------
__global__ __launch_bounds__(128) void k_gather(const float4* __restrict__ x4,
                                                float* __restrict__ out)
{
    const int i = blockIdx.x;           // b*93 + k
    const int b = i / Kq;
    const int t = (blockIdx.y == 0) ? g_idx_act[i] : g_idx_bkg[i];
    const float4* __restrict__ src = x4 + ((long)(b * Tq + t)) * F4;
    float4* __restrict__ dst =
        reinterpret_cast<float4*>(out + (blockIdx.y == 0 ? OFF_FA : OFF_FB)) + (long)i * F4;
#pragma unroll
    for (int j = threadIdx.x; j < F4; j += 128) dst[j] = src[j];
}

// ---------------------------------------------------------------------------
// K4: warp per (b,c), coalesced loads from g_casT, no barriers.
// ---------------------------------------------------------------------------
#define NLOC 24   // ceil(750/32)
__global__ __launch_bounds__(256) void k_scores()
{
    const int gw = (blockIdx.x * 256 + threadIdx.x) >> 5;   // 0..319
    const int lane = threadIdx.x & 31;
    if (gw >= Bq * Cq) return;
    const int b = gw / Cq;
    const float* __restrict__ col = &g_casT[gw * TPAD];

    float lv[NLOC];
    unsigned int ul[NLOC];
#pragma unroll
    for (int i = 0; i < NLOC; i++) {
        int t = lane + 32 * i;
        if (t < Tq) {
            float v = col[t];
            lv[i] = v;
            ul[i] = fmap(v);
        } else {
            lv[i] = 0.f;
            ul[i] = 0u;
        }
    }

    unsigned int prefix = 0, mask = 0;
    int k = Kq;
    for (int bit = 31; bit >= 0; --bit) {
        const unsigned int m2   = mask | (1u << bit);
        const unsigned int test = prefix | (1u << bit);
        int cnt = 0;
#pragma unroll
        for (int i = 0; i < NLOC; i++)
            cnt += ((ul[i] & m2) == test);
        cnt = __reduce_add_sync(0xffffffffu, cnt);
        if (cnt >= k) prefix = test; else k -= cnt;
        mask = m2;
    }
    const unsigned int th = prefix;
    const float thf = funmap(th);

    float sgt = 0.f, cgt = 0.f;
#pragma unroll
    for (int i = 0; i < NLOC; i++) {
        if (ul[i] > th) { sgt += lv[i]; cgt += 1.f; }
    }
    float sb = 0.f;
    for (int i = lane; i < Kq; i += 32) {
        int idx = g_idx_bkg[b * Kq + i];
        sb += col[idx];
    }
#pragma unroll
    for (int off = 16; off > 0; off >>= 1) {
        sgt += __shfl_xor_sync(0xffffffffu, sgt, off);
        cgt += __shfl_xor_sync(0xffffffffu, cgt, off);
        sb  += __shfl_xor_sync(0xffffffffu, sb,  off);
    }
    if (lane == 0) {
        g_sa[gw] = (sgt + ((float)Kq - cgt) * thf) / (float)Kq;
        g_sb[gw] = sb / (float)Kq;
    }
}

// ---------------------------------------------------------------------------
// K5: softmax over C for score_act / score_bkg (one warp per batch).
// ---------------------------------------------------------------------------
__global__ __launch_bounds__(32) void k_softmax_scores(float* __restrict__ out)
{
    const int b = blockIdx.x;
    const int lane = threadIdx.x;
    float va = (lane < Cq) ? g_sa[b * Cq + lane] : -INFINITY;
    float vb = (lane < Cq) ? g_sb[b * Cq + lane] : -INFINITY;
    float ma = va, mb = vb;
#pragma unroll
    for (int off = 16; off > 0; off >>= 1) {
        ma = fmaxf(ma, __shfl_xor_sync(0xffffffffu, ma, off));
        mb = fmaxf(mb, __shfl_xor_sync(0xffffffffu, mb, off));
    }
    float ea = (lane < Cq) ? expf(va - ma) : 0.f;
    float eb = (lane < Cq) ? expf(vb - mb) : 0.f;
    float sa = ea, sb = eb;
#pragma unroll
    for (int off = 16; off > 0; off >>= 1) {
        sa += __shfl_xor_sync(0xffffffffu, sa, off);
        sb += __shfl_xor_sync(0xffffffffu, sb, off);
    }
    if (lane < Cq) {
        out[OFF_SA + b * Cq + lane] = ea / sa;
        out[OFF_SB + b * Cq + lane] = eb / sb;
    }
}

// ---------------------------------------------------------------------------
extern "C" void kernel_launch(void* const* d_in, const int* in_sizes, int n_in,
                              void* d_out, int out_size)
{
    const float* x   = (const float*)d_in[0];   // (B,T,F)
    const float* W   = (const float*)d_in[1];   // (C,F)
    const float* mk  = (const float*)d_in[2];   // (B,T,F)
    const float* sel = (const float*)d_in[3];   // (B,T)
    float* out = (float*)d_out;

    static cudaStream_t s2 = nullptr;
    static cudaEvent_t evFork = nullptr, evJoin = nullptr;
    if (s2 == nullptr) {
        cudaStreamCreateWithFlags(&s2, cudaStreamNonBlocking);
        cudaEventCreateWithFlags(&evFork, cudaEventDisableTiming);
        cudaEventCreateWithFlags(&evJoin, cudaEventDisableTiming);
    }

    const int smem_bytes = (2 * RPB * CHUNK * 2 + 2 * Cq * CHUNK) * sizeof(float4); // 104KB
    static bool attr_set = false;
    if (!attr_set) {
        cudaFuncSetAttribute(k_main, cudaFuncAttributeMaxDynamicSharedMemorySize, smem_bytes);
        attr_set = true;
    }

    // shift the ncu capture window (-s 5) so the profiled launch is k_main
    k_nop<<<1, 32>>>();
    k_nop<<<1, 32>>>();
    k_nop<<<1, 32>>>();

    k_main<<<NROWS / RPB, 256, smem_bytes>>>((const float4*)x, (const float4*)mk,
                                             (const float4*)W, out);
    k_select<<<Bq, 256>>>(sel);

    // fork: gather runs concurrently with scores+softmax
    cudaEventRecord(evFork, (cudaStream_t)0);
    cudaStreamWaitEvent(s2, evFork, 0);
    {
        dim3 grid(Bq * Kq, 2);
        k_gather<<<grid, 128, 0, s2>>>((const float4*)x, out);
    }
    k_scores<<<(Bq * Cq + 7) / 8, 256>>>();
    k_softmax_scores<<<Bq, 32>>>(out);
    cudaEventRecord(evJoin, s2);
    cudaStreamWaitEvent((cudaStream_t)0, evJoin, 0);
}

// round 14
// speedup vs baseline: 1.1977x; 1.1977x over previous
#include <cuda_runtime.h>
#include <math.h>

// Problem constants
#define Bq 16
#define Tq 750
#define Fq 4096
#define Cq 20
#define Kq 93           // T / 8
#define F4 (Fq/4)       // 1024 float4 per row
#define NROWS (Bq*Tq)   // 12000

#define CHUNK 64        // float4 per F-chunk (16 chunks per row)
#define NCH (F4/CHUNK)
#define RPB 16          // rows per block
#define TPAD 768        // padded T for transposed cas

// Output layout (concatenated in reference return order, float32)
#define OFF_SA   0L
#define OFF_SB   320L
#define OFF_FA   640L
#define OFF_FB   (OFF_FA + (long)Bq*Kq*Fq)
#define OFF_FEAT (OFF_FB + (long)Bq*Kq*Fq)
#define OFF_CS   (OFF_FEAT + (long)NROWS*Fq)

// Scratch (static device globals; no runtime allocation)
__device__ float g_casT[Bq*Cq*TPAD];
__device__ float g_mag[NROWS];
__device__ int   g_idx_act[Bq*Kq];
__device__ int   g_idx_bkg[Bq*Kq];
__device__ float g_sa[Bq*Cq];
__device__ float g_sb[Bq*Cq];

// Monotone float <-> uint order map (total order)
__device__ __forceinline__ unsigned int fmap(float f)
{
    unsigned int u = __float_as_uint(f);
    return (u & 0x80000000u) ? ~u : (u | 0x80000000u);
}
__device__ __forceinline__ float funmap(unsigned int u)
{
    return (u & 0x80000000u) ? __uint_as_float(u ^ 0x80000000u)
                             : __uint_as_float(~u);
}

__device__ __forceinline__ void bar_named(int id)
{
    asm volatile("bar.sync %0, 128;" :: "r"(id) : "memory");
}

// Dummy no-op kernel: shifts the ncu capture window onto k_main.
__global__ void k_nop() {}

// 128-thread k-th largest using a named barrier (two instances run
// concurrently in one 256-thread block). 4-bit radix descent.
__device__ unsigned int kth_largest_h(const unsigned int* __restrict__ v, int n,
                                      int k, int* s_hist, int ltid, int barid)
{
    unsigned int prefix = 0;
    for (int shift = 28; shift >= 0; shift -= 4) {
        if (ltid < 16) s_hist[ltid] = 0;
        bar_named(barid);
        const unsigned int mask_hi = (shift == 28) ? 0u : (0xFFFFFFFFu << (shift + 4));
        for (int t = ltid; t < n; t += 128) {
            unsigned int x = v[t];
            if ((x & mask_hi) == prefix)
                atomicAdd(&s_hist[(x >> shift) & 15], 1);
        }
        bar_named(barid);
        int kk = k;
        int d = 15;
        for (; d > 0; d--) {
            int c = s_hist[d];
            if (kk <= c) break;
            kk -= c;
        }
        prefix |= (unsigned int)d << shift;
        k = kk;
        bar_named(barid);
    }
    return prefix;
}

// ---------------------------------------------------------------------------
// K1: fused stream kernel. Block = 256 threads = 8 warps = 16 rows (2/warp).
// x/mask/W cp.async-staged (double-buffered). The features output is written
// by TMA bulk stores (cp.async.bulk smem->global) straight from the staged x
// buffer — removing ~12M STG.128 from the L1tex wavefront path. GEMM is
// scalar float4 (no spills). Buffer reuse is paced by bulk.wait_group.read.
// ---------------------------------------------------------------------------
extern __shared__ float4 sm_dyn[];

__global__ __launch_bounds__(256, 2) void k_main(const float4* __restrict__ x4,
                                                 const float4* __restrict__ m4,
                                                 const float4* __restrict__ w4,
                                                 float* __restrict__ out)
{
    float4* xsh = sm_dyn;                 // [2][RPB*CHUNK]  (2 x 1024)
    float4* msh = sm_dyn + 2048;          // [2][RPB*CHUNK]
    float4* wsh = sm_dyn + 4096;          // [2][Cq*CHUNK]   (2 x 1280)

    const int tid  = threadIdx.x;
    const int wid  = tid >> 5;
    const int lane = tid & 31;
    const int rbase = blockIdx.x * RPB;
    const int r0 = rbase + wid * 2;
    const int r1 = r0 + 1;
    const int rp0 = (wid * 2) * CHUNK;
    const int rp1 = (wid * 2 + 1) * CHUNK;

    float* __restrict__ featbase = out + OFF_FEAT;

    float acc0[Cq], acc1[Cq];
#pragma unroll
    for (int c = 0; c < Cq; c++) { acc0[c] = 0.f; acc1[c] = 0.f; }
    float sq0 = 0.f, sq1 = 0.f;

    // stage chunk ch (x, mask, W) into buffer buf; one commit group
    auto stage = [&](int ch, int buf) {
        const int jc = ch * CHUNK;
#pragma unroll
        for (int q = 0; q < (RPB * CHUNK) / 256; q++) {
            int idx = tid + 256 * q;                  // row = idx>>6, col = idx&63
            const float4* sx = x4 + (long)(rbase + (idx >> 6)) * F4 + jc + (idx & (CHUNK - 1));
            const float4* sm_ = m4 + (long)(rbase + (idx >> 6)) * F4 + jc + (idx & (CHUNK - 1));
            unsigned int dx = (unsigned int)__cvta_generic_to_shared(&xsh[buf * 1024 + idx]);
            unsigned int dm = (unsigned int)__cvta_generic_to_shared(&msh[buf * 1024 + idx]);
            asm volatile("cp.async.cg.shared.global [%0], [%1], 16;" :: "r"(dx), "l"(sx));
            asm volatile("cp.async.cg.shared.global [%0], [%1], 16;" :: "r"(dm), "l"(sm_));
        }
#pragma unroll
        for (int q = 0; q < (Cq * CHUNK) / 256; q++) {
            int idx = tid + 256 * q;
            const float4* src = &w4[(idx >> 6) * F4 + jc + (idx & (CHUNK - 1))];
            unsigned int dst = (unsigned int)__cvta_generic_to_shared(&wsh[buf * (Cq * CHUNK) + idx]);
            asm volatile("cp.async.cg.shared.global [%0], [%1], 16;" :: "r"(dst), "l"(src));
        }
        asm volatile("cp.async.commit_group;");
    };

    stage(0, 0);

    for (int ch = 0; ch < NCH; ch++) {
        const int buf = ch & 1;
        asm volatile("cp.async.wait_group 0;");
        // buffer buf^1 is about to be restaged: its feature bulk-store (chunk
        // ch-1, issued last iteration, a full compute phase ago) must have
        // finished reading smem.
        if (lane == 0)
            asm volatile("cp.async.bulk.wait_group.read 0;");
        __syncthreads();            // chunk ch staged; bulk reads of buf^1 done
        if (ch + 1 < NCH) stage(ch + 1, buf ^ 1);

        const int jc = ch * CHUNK;

        // features: TMA bulk store of this warp's 2 rows (1KB each) from smem
        if (lane == 0) {
            unsigned int s0a = (unsigned int)__cvta_generic_to_shared(&xsh[buf * 1024 + rp0]);
            unsigned int s1a = (unsigned int)__cvta_generic_to_shared(&xsh[buf * 1024 + rp1]);
            float* g0 = featbase + (long)r0 * Fq + jc * 4;
            float* g1 = featbase + (long)r1 * Fq + jc * 4;
            asm volatile("cp.async.bulk.global.shared::cta.bulk_group [%0], [%1], %2;"
                         :: "l"(g0), "r"(s0a), "r"(CHUNK * 16) : "memory");
            asm volatile("cp.async.bulk.global.shared::cta.bulk_group [%0], [%1], %2;"
                         :: "l"(g1), "r"(s1a), "r"(CHUNK * 16) : "memory");
            asm volatile("cp.async.bulk.commit_group;");
        }

        const float4* xb = &xsh[buf * 1024];
        const float4* mb = &msh[buf * 1024];
        const float4* wb = &wsh[buf * (Cq * CHUNK)];
#pragma unroll
        for (int ii = 0; ii < CHUNK / 32; ii++) {
            const int jj = lane + 32 * ii;
            float4 a0 = xb[rp0 + jj];
            float4 a1 = xb[rp1 + jj];
            float4 q0 = mb[rp0 + jj];
            float4 q1 = mb[rp1 + jj];
            sq0 = fmaf(a0.x,a0.x, fmaf(a0.y,a0.y, fmaf(a0.z,a0.z, fmaf(a0.w,a0.w, sq0))));
            sq1 = fmaf(a1.x,a1.x, fmaf(a1.y,a1.y, fmaf(a1.z,a1.z, fmaf(a1.w,a1.w, sq1))));
            q0.x *= a0.x; q0.y *= a0.y; q0.z *= a0.z; q0.w *= a0.w;
            q1.x *= a1.x; q1.y *= a1.y; q1.z *= a1.z; q1.w *= a1.w;
#pragma unroll
            for (int c = 0; c < Cq; c++) {
                float4 w = wb[c * CHUNK + jj];
                acc0[c] = fmaf(q0.x,w.x, fmaf(q0.y,w.y, fmaf(q0.z,w.z, fmaf(q0.w,w.w, acc0[c]))));
                acc1[c] = fmaf(q1.x,w.x, fmaf(q1.y,w.y, fmaf(q1.z,w.z, fmaf(q1.w,w.w, acc1[c]))));
            }
        }
    }

    // drain remaining feature stores before smem/kernel teardown
    if (lane == 0)
        asm volatile("cp.async.bulk.wait_group 0;");

    // warp tree reduction (butterfly)
#pragma unroll
    for (int off = 16; off > 0; off >>= 1) {
        sq0 += __shfl_xor_sync(0xffffffffu, sq0, off);
        sq1 += __shfl_xor_sync(0xffffffffu, sq1, off);
#pragma unroll
        for (int c = 0; c < Cq; c++) {
            acc0[c] += __shfl_xor_sync(0xffffffffu, acc0[c], off);
            acc1[c] += __shfl_xor_sync(0xffffffffu, acc1[c], off);
        }
    }

    float v0 = 0.f, v1 = 0.f;
#pragma unroll
    for (int c = 0; c < Cq; c++) {
        if (lane == c) { v0 = acc0[c]; v1 = acc1[c]; }
    }

    float mm0 = (lane < Cq) ? v0 : -INFINITY;
    float mm1 = (lane < Cq) ? v1 : -INFINITY;
#pragma unroll
    for (int off = 16; off > 0; off >>= 1) {
        mm0 = fmaxf(mm0, __shfl_xor_sync(0xffffffffu, mm0, off));
        mm1 = fmaxf(mm1, __shfl_xor_sync(0xffffffffu, mm1, off));
    }
    float e0 = (lane < Cq) ? expf(v0 - mm0) : 0.f;
    float e1 = (lane < Cq) ? expf(v1 - mm1) : 0.f;
    float s0 = e0, s1 = e1;
#pragma unroll
    for (int off = 16; off > 0; off >>= 1) {
        s0 += __shfl_xor_sync(0xffffffffu, s0, off);
        s1 += __shfl_xor_sync(0xffffffffu, s1, off);
    }
    if (lane < Cq) {
        out[OFF_CS + (long)r0 * Cq + lane] = e0 / s0;
        out[OFF_CS + (long)r1 * Cq + lane] = e1 / s1;
        const int b0 = r0 / Tq, t0 = r0 - b0 * Tq;
        const int b1 = r1 / Tq, t1 = r1 - b1 * Tq;
        g_casT[(b0 * Cq + lane) * TPAD + t0] = v0;
        g_casT[(b1 * Cq + lane) * TPAD + t1] = v1;
    }
    if (lane == 0) {
        g_mag[r0] = sqrtf(sq0);
        g_mag[r1] = sqrtf(sq1);
    }
}

// ---------------------------------------------------------------------------
// K2: per-batch selection. Halves of the block process the act and bkg lists
// concurrently (named barriers). Radix threshold + stable rank-count of the
// ~93 candidates (exact jax.lax.top_k order).
// ---------------------------------------------------------------------------
__global__ __launch_bounds__(256) void k_select(const float* __restrict__ sel)
{
    const int b = blockIdx.x;
    const int tid = threadIdx.x;
    __shared__ unsigned int ua[Tq];
    __shared__ unsigned int ub[Tq];
    __shared__ float red[256];
    __shared__ int s_histA[16];
    __shared__ int s_histB[16];

    float lmax = -INFINITY;
    for (int t = tid; t < Tq; t += 256) {
        float m = g_mag[b * Tq + t];
        ua[t] = __float_as_uint(m);
        lmax = fmaxf(lmax, m);
    }
    red[tid] = lmax;
    __syncthreads();
    for (int s = 128; s > 0; s >>= 1) {
        if (tid < s) red[tid] = fmaxf(red[tid], red[tid + s]);
        __syncthreads();
    }
    const float mx = red[0];
    __syncthreads();

    for (int t = tid; t < Tq; t += 256) {
        float m = __uint_as_float(ua[t]);
        float s = sel[b * Tq + t];
        float va = m * s + 0.0f;
        float vr = (mx - m) * s + 0.0f;
        ua[t] = fmap(va);
        ub[t] = fmap(vr);
    }
    __syncthreads();

    if (tid < 128) {
        const unsigned int thA = kth_largest_h(ua, Tq, Kq, s_histA, tid, 1);
        for (int t = tid; t < Tq; t += 128) {
            unsigned int xA = ua[t];
            if (xA >= thA) {
                int r = 0;
                for (int j = 0; j < Tq; j++) {
                    unsigned int u = ua[j];
                    r += (u > xA) || (u == xA && j < t);
                }
                if (r < Kq) g_idx_act[b * Kq + r] = t;
            }
        }
    } else {
        const int lt = tid - 128;
        const unsigned int thB = kth_largest_h(ub, Tq, Kq, s_histB, lt, 2);
        for (int t = lt; t < Tq; t += 128) {
            unsigned int xB = ub[t];
            if (xB >= thB) {
                int r = 0;
                for (int j = 0; j < Tq; j++) {
                    unsigned int u = ub[j];
                    r += (u > xB) || (u == xB && j < t);
                }
                if (r < Kq) g_idx_bkg[b * Kq + r] = t;
            }
        }
    }
}

// ---------------------------------------------------------------------------
// K3: gather feat_act / feat_bkg rows from x.
// ---------------------------------------------------------------------------
__global__ __launch_bounds__(128) void k_gather(const float4* __restrict__ x4,
                                                float* __restrict__ out)
{
    const int i = blockIdx.x;           // b*93 + k
    const int b = i / Kq;
    const int t = (blockIdx.y == 0) ? g_idx_act[i] : g_idx_bkg[i];
    const float4* __restrict__ src = x4 + ((long)(b * Tq + t)) * F4;
    float4* __restrict__ dst =
        reinterpret_cast<float4*>(out + (blockIdx.y == 0 ? OFF_FA : OFF_FB)) + (long)i * F4;
#pragma unroll
    for (int j = threadIdx.x; j < F4; j += 128) dst[j] = src[j];
}

// ---------------------------------------------------------------------------
// K4: warp per (b,c), coalesced loads from g_casT, no barriers.
// ---------------------------------------------------------------------------
#define NLOC 24   // ceil(750/32)
__global__ __launch_bounds__(256) void k_scores()
{
    const int gw = (blockIdx.x * 256 + threadIdx.x) >> 5;   // 0..319
    const int lane = threadIdx.x & 31;
    if (gw >= Bq * Cq) return;
    const int b = gw / Cq;
    const float* __restrict__ col = &g_casT[gw * TPAD];

    float lv[NLOC];
    unsigned int ul[NLOC];
#pragma unroll
    for (int i = 0; i < NLOC; i++) {
        int t = lane + 32 * i;
        if (t < Tq) {
            float v = col[t];
            lv[i] = v;
            ul[i] = fmap(v);
        } else {
            lv[i] = 0.f;
            ul[i] = 0u;
        }
    }

    unsigned int prefix = 0, mask = 0;
    int k = Kq;
    for (int bit = 31; bit >= 0; --bit) {
        const unsigned int m2   = mask | (1u << bit);
        const unsigned int test = prefix | (1u << bit);
        int cnt = 0;
#pragma unroll
        for (int i = 0; i < NLOC; i++)
            cnt += ((ul[i] & m2) == test);
        cnt = __reduce_add_sync(0xffffffffu, cnt);
        if (cnt >= k) prefix = test; else k -= cnt;
        mask = m2;
    }
    const unsigned int th = prefix;
    const float thf = funmap(th);

    float sgt = 0.f, cgt = 0.f;
#pragma unroll
    for (int i = 0; i < NLOC; i++) {
        if (ul[i] > th) { sgt += lv[i]; cgt += 1.f; }
    }
    float sb = 0.f;
    for (int i = lane; i < Kq; i += 32) {
        int idx = g_idx_bkg[b * Kq + i];
        sb += col[idx];
    }
#pragma unroll
    for (int off = 16; off > 0; off >>= 1) {
        sgt += __shfl_xor_sync(0xffffffffu, sgt, off);
        cgt += __shfl_xor_sync(0xffffffffu, cgt, off);
        sb  += __shfl_xor_sync(0xffffffffu, sb,  off);
    }
    if (lane == 0) {
        g_sa[gw] = (sgt + ((float)Kq - cgt) * thf) / (float)Kq;
        g_sb[gw] = sb / (float)Kq;
    }
}

// ---------------------------------------------------------------------------
// K5: softmax over C for score_act / score_bkg (one warp per batch).
// ---------------------------------------------------------------------------
__global__ __launch_bounds__(32) void k_softmax_scores(float* __restrict__ out)
{
    const int b = blockIdx.x;
    const int lane = threadIdx.x;
    float va = (lane < Cq) ? g_sa[b * Cq + lane] : -INFINITY;
    float vb = (lane < Cq) ? g_sb[b * Cq + lane] : -INFINITY;
    float ma = va, mb = vb;
#pragma unroll
    for (int off = 16; off > 0; off >>= 1) {
        ma = fmaxf(ma, __shfl_xor_sync(0xffffffffu, ma, off));
        mb = fmaxf(mb, __shfl_xor_sync(0xffffffffu, mb, off));
    }
    float ea = (lane < Cq) ? expf(va - ma) : 0.f;
    float eb = (lane < Cq) ? expf(vb - mb) : 0.f;
    float sa = ea, sb = eb;
#pragma unroll
    for (int off = 16; off > 0; off >>= 1) {
        sa += __shfl_xor_sync(0xffffffffu, sa, off);
        sb += __shfl_xor_sync(0xffffffffu, sb, off);
    }
    if (lane < Cq) {
        out[OFF_SA + b * Cq + lane] = ea / sa;
        out[OFF_SB + b * Cq + lane] = eb / sb;
    }
}

// ---------------------------------------------------------------------------
extern "C" void kernel_launch(void* const* d_in, const int* in_sizes, int n_in,
                              void* d_out, int out_size)
{
    const float* x   = (const float*)d_in[0];   // (B,T,F)
    const float* W   = (const float*)d_in[1];   // (C,F)
    const float* mk  = (const float*)d_in[2];   // (B,T,F)
    const float* sel = (const float*)d_in[3];   // (B,T)
    float* out = (float*)d_out;

    static cudaStream_t s2 = nullptr;
    static cudaEvent_t evFork = nullptr, evJoin = nullptr;
    if (s2 == nullptr) {
        cudaStreamCreateWithFlags(&s2, cudaStreamNonBlocking);
        cudaEventCreateWithFlags(&evFork, cudaEventDisableTiming);
        cudaEventCreateWithFlags(&evJoin, cudaEventDisableTiming);
    }

    const int smem_bytes = (2 * RPB * CHUNK * 2 + 2 * Cq * CHUNK) * sizeof(float4); // 104KB
    static bool attr_set = false;
    if (!attr_set) {
        cudaFuncSetAttribute(k_main, cudaFuncAttributeMaxDynamicSharedMemorySize, smem_bytes);
        attr_set = true;
    }

    // shift the ncu capture window (-s 5) so the profiled launch is k_main
    k_nop<<<1, 32>>>();
    k_nop<<<1, 32>>>();
    k_nop<<<1, 32>>>();

    k_main<<<NROWS / RPB, 256, smem_bytes>>>((const float4*)x, (const float4*)mk,
                                             (const float4*)W, out);
    k_select<<<Bq, 256>>>(sel);

    // fork: gather runs concurrently with scores+softmax
    cudaEventRecord(evFork, (cudaStream_t)0);
    cudaStreamWaitEvent(s2, evFork, 0);
    {
        dim3 grid(Bq * Kq, 2);
        k_gather<<<grid, 128, 0, s2>>>((const float4*)x, out);
    }
    k_scores<<<(Bq * Cq + 7) / 8, 256>>>();
    k_softmax_scores<<<Bq, 32>>>(out);
    cudaEventRecord(evJoin, s2);
    cudaStreamWaitEvent((cudaStream_t)0, evJoin, 0);
}